// round 9
// baseline (speedup 1.0000x reference)
#include <cuda_runtime.h>
#include <cuda_bf16.h>
#include <cstdint>
#include <cstddef>

#define BATCH 8
#define NPT   4096
#define CH    64
#define NCOL  (BATCH*NPT*16)         /* 524288 columns */
#define NTIL  (NCOL/128)             /* 4096 tensor tiles */
#define TPC   8                      /* tiles per CTA */
#define NGRID (NTIL/TPC)             /* 512 gemm CTAs */

/* ------------------------- device scratch (no allocs) ------------------- */
__device__ float4 d_psort[BATCH*NPT];
__device__ int    d_pidx [BATCH*NPT];
__device__ float4 d_rel  [NCOL];
__device__ float  d_relstats[256*9];
__device__ float4 d_w0eff[CH];
__device__ float  d_z1stats[(size_t)NGRID*128];
__device__ double d_z1stats2[64*128];
__device__ float2 d_a1c1[CH];

__device__ __forceinline__ float sq3(float x, float y, float z) {
    return __fadd_rn(__fadd_rn(__fmul_rn(x,x), __fmul_rn(y,y)), __fmul_rn(z,z));
}

/* ------------------------- warp-mma helpers (sm_80+ portable) ----------- */
__device__ __forceinline__ uint32_t smem_u32(const void* p) {
    uint32_t a;
    asm("{ .reg .u64 t; cvta.to.shared.u64 t, %1; cvt.u32.u64 %0, t; }" : "=r"(a) : "l"(p));
    return a;
}
#define SWZ(o) ((o) ^ (((o) >> 3) & 0x70))

__device__ __forceinline__ void ldsm4(uint32_t addr, uint32_t r[4]) {
    asm volatile("ldmatrix.sync.aligned.m8n8.x4.shared.b16 {%0,%1,%2,%3}, [%4];"
        : "=r"(r[0]), "=r"(r[1]), "=r"(r[2]), "=r"(r[3]) : "r"(addr));
}
__device__ __forceinline__ void mma_bf16(float* c, const uint32_t* a,
                                         uint32_t b0, uint32_t b1) {
    asm volatile("mma.sync.aligned.m16n8k16.row.col.f32.bf16.bf16.f32 "
        "{%0,%1,%2,%3}, {%4,%5,%6,%7}, {%8,%9}, {%0,%1,%2,%3};"
        : "+f"(c[0]), "+f"(c[1]), "+f"(c[2]), "+f"(c[3])
        : "r"(a[0]), "r"(a[1]), "r"(a[2]), "r"(a[3]), "r"(b0), "r"(b1));
}
__device__ __forceinline__ uint32_t pk(float a, float b) {
    __nv_bfloat162 h = __floats2bfloat162_rn(a, b);
    return *(uint32_t*)&h;
}
__device__ __forceinline__ void split2(float a, float b, uint32_t& hi, uint32_t& lo) {
    __nv_bfloat16 ah = __float2bfloat16_rn(a), bh = __float2bfloat16_rn(b);
    float ar = a - __bfloat162float(ah), br = b - __bfloat162float(bh);
    hi = (uint32_t)__bfloat16_as_ushort(ah) | ((uint32_t)__bfloat16_as_ushort(bh) << 16);
    lo = pk(ar, br);
}

/* smem layout (bytes) */
#define SM_AHI   0
#define SM_ALO   16384
#define SM_BHI   32768
#define SM_BLO   40960
#define SM_W0    49152
#define SM_STATS 50176
#define SM_AC    50176
#define SM_BIAS  50688
#define SMEM_G   52224

/* ------------------------- 1. bucket scatter (desc by |p|^2) ------------- */
/* bucket = 1023 - (bits(sq)>>21): monotone desc, within-bucket ratio <=1.25 */
__global__ __launch_bounds__(1024) void bucket_kernel(const float* __restrict__ xyz) {
    __shared__ int hist[1024];
    __shared__ int scan[1024];
    __shared__ int cur[1024];
    int b = blockIdx.x, tid = threadIdx.x;
    const float* xb = xyz + (size_t)b * 3 * NPT;

    hist[tid] = 0;
    __syncthreads();

    float xs[4], ys[4], zs[4], sqs[4];
    int bks[4];
    #pragma unroll
    for (int e = 0; e < 4; e++) {
        int i = e * 1024 + tid;
        float x = xb[i], y = xb[NPT + i], z = xb[2*NPT + i];
        float sq = sq3(x, y, z);
        unsigned int u = __float_as_uint(sq);
        int bk = 1023 - (int)(u >> 21);
        xs[e] = x; ys[e] = y; zs[e] = z; sqs[e] = sq; bks[e] = bk;
        atomicAdd(&hist[bk], 1);
    }
    __syncthreads();
    /* inclusive scan (Hillis-Steele) */
    scan[tid] = hist[tid];
    __syncthreads();
    for (int off = 1; off < 1024; off <<= 1) {
        int v = (tid >= off) ? scan[tid - off] : 0;
        __syncthreads();
        scan[tid] += v;
        __syncthreads();
    }
    cur[tid] = scan[tid] - hist[tid];   /* exclusive prefix */
    __syncthreads();

    #pragma unroll
    for (int e = 0; e < 4; e++) {
        int pos = atomicAdd(&cur[bks[e]], 1);
        d_psort[(b << 12) + pos] = make_float4(xs[e], ys[e], zs[e], sqs[e]);
        d_pidx [(b << 12) + pos] = e * 1024 + tid;
    }
}

/* ------------------------- 2. kNN (farthest-16 after dropping rank 0) ---- */
__global__ __launch_bounds__(128) void knn_kernel(const float* __restrict__ xyz) {
    __shared__ float4 tP[512];
    __shared__ int    tI[512];
    __shared__ float  red[128];

    int b   = blockIdx.y;
    int tid = threadIdx.x;
    int i   = blockIdx.x * 128 + tid;
    const float* xb = xyz + (size_t)b * 3 * NPT;

    float px = xb[i], py = xb[NPT + i], pz = xb[2*NPT + i];
    float sqi  = sq3(px, py, pz);
    float si_r = sqrtf(sqi);

    unsigned long long heap[17];
    #pragma unroll
    for (int r = 0; r < 17; r++) heap[r] = 0ull;
    float thrF = __uint_as_float(0x7fffffffu);
    float B2   = -1.0f;
    bool  dead = false;

    for (int t0 = 0; t0 < NPT; t0 += 512) {
        for (int s = tid; s < 512; s += 128) {
            tP[s] = d_psort[(b << 12) + t0 + s];
            tI[s] = d_pidx [(b << 12) + t0 + s];
        }
        __syncthreads();
        if (!__all_sync(0xffffffffu, dead)) {
            #pragma unroll 4
            for (int u = 0; u < 512; u++) {
                if (!dead) {
                    float4 q = tP[u];
                    if (q.w < B2) dead = true;   /* B2 pre-scaled by 0.8 for buckets */
                    else {
                        float dot = fmaf(pz, q.z, fmaf(py, q.y, __fmul_rn(px, q.x)));
                        float d   = __fsub_rn(__fadd_rn(sqi, q.w), __fmul_rn(2.0f, dot));
                        if (!(d < thrF)) {
                            int j2 = tI[u];
                            unsigned int bits = __float_as_uint(d);
                            unsigned int mono = bits ^ ((unsigned int)(((int)bits) >> 31) | 0x80000000u);
                            unsigned long long key =
                                ((unsigned long long)mono << 32) | (unsigned int)(~j2);
                            if (key > heap[16]) {
                                heap[16] = key;
                                #pragma unroll
                                for (int r = 16; r > 0; r--) {
                                    unsigned long long a_ = heap[r-1], c_ = heap[r];
                                    bool sw = c_ > a_;
                                    heap[r-1] = sw ? c_ : a_;
                                    heap[r]   = sw ? a_ : c_;
                                }
                                unsigned int h16 = (unsigned int)(heap[16] >> 32);
                                thrF = __uint_as_float((h16 & 0x80000000u) ? (h16 ^ 0x80000000u)
                                                                           : ~h16);
                                float L   = __fmaf_rn(-1e-4f, thrF, thrF) - 1e-6f;
                                float sL  = sqrtf(L);
                                float bb2 = sL - si_r;
                                B2 = (bb2 > 0.0f) ? bb2 * bb2 * 0.8f : -1.0f;
                            }
                        }
                    }
                }
                if ((u & 63) == 63 && __all_sync(0xffffffffu, dead)) break;
            }
        }
        if (__syncthreads_and(dead)) break;
    }

    float sx=0,sy=0,sz=0,sxx=0,syy=0,szz=0,sxy=0,sxz=0,syz=0;
    size_t base = ((size_t)((b << 12) + i)) << 4;
    #pragma unroll
    for (int r = 1; r < 17; r++) {
        int j2 = ~((unsigned int)heap[r]);
        float rx = __fsub_rn(xb[j2],         px);
        float ry = __fsub_rn(xb[NPT  + j2],  py);
        float rz = __fsub_rn(xb[2*NPT + j2], pz);
        d_rel[base + (r - 1)] = make_float4(rx, ry, rz, 0.0f);
        sx += rx; sy += ry; sz += rz;
        sxx = fmaf(rx, rx, sxx); syy = fmaf(ry, ry, syy); szz = fmaf(rz, rz, szz);
        sxy = fmaf(rx, ry, sxy); sxz = fmaf(rx, rz, sxz); syz = fmaf(ry, rz, syz);
    }
    float st[9] = {sx, sy, sz, sxx, syy, szz, sxy, sxz, syz};
    int blk = b * 32 + blockIdx.x;
    for (int s = 0; s < 9; s++) {
        __syncthreads();
        red[tid] = st[s];
        __syncthreads();
        for (int off = 64; off; off >>= 1) {
            if (tid < off) red[tid] += red[tid + off];
            __syncthreads();
        }
        if (tid == 0) d_relstats[blk * 9 + s] = red[0];
    }
}

/* ------------------------- 3. fold block-0 conv+BN+relu ------------------ */
__global__ __launch_bounds__(64) void prep_kernel(const float* __restrict__ w1,
                                                  const float* __restrict__ b1,
                                                  const float* __restrict__ gamma,
                                                  const float* __restrict__ beta) {
    __shared__ double S[9];
    int t = threadIdx.x;
    if (t < 9) {
        double acc = 0.0;
        for (int v = 0; v < 256; v++) acc += (double)d_relstats[v * 9 + t];
        S[t] = acc;
    }
    __syncthreads();
    double inv = 1.0 / (double)NCOL;
    double mx = S[0]*inv, my = S[1]*inv, mz = S[2]*inv;
    double cxx = S[3]*inv - mx*mx, cyy = S[4]*inv - my*my, czz = S[5]*inv - mz*mz;
    double cxy = S[6]*inv - mx*my, cxz = S[7]*inv - mx*mz, cyz = S[8]*inv - my*mz;
    double wx = w1[t*3], wy = w1[t*3+1], wz = w1[t*3+2];
    double var = wx*(wx*cxx + 2.0*(wy*cxy + wz*cxz)) + wy*(wy*cyy + 2.0*wz*cyz) + wz*wz*czz;
    double mu  = wx*mx + wy*my + wz*mz + (double)b1[t];
    float aa = gamma[t] * rsqrtf((float)var + 1e-5f);
    float cc = beta[t] - (float)mu * aa;
    d_w0eff[t] = make_float4(aa*(float)wx, aa*(float)wy, aa*(float)wz, fmaf(aa, b1[t], cc));
}

/* -------- shared device code: build A (h0 split) and B (w2 split) -------- */
__device__ __forceinline__ void build_B(char* smraw, const float* __restrict__ w2, int tid) {
    int n = tid >> 1, k0 = (tid & 1) * 32;
    const float* wrow = w2 + n * 64 + k0;
    #pragma unroll
    for (int k = 0; k < 32; k += 4) {
        float4 v = *(const float4*)(wrow + k);
        uint32_t h0, h1, l0, l1;
        split2(v.x, v.y, h0, l0); split2(v.z, v.w, h1, l1);
        uint32_t off = SWZ((uint32_t)(n * 128 + (k0 + k) * 2));
        *(uint2*)(smraw + SM_BHI + off) = make_uint2(h0, h1);
        *(uint2*)(smraw + SM_BLO + off) = make_uint2(l0, l1);
    }
}
__device__ __forceinline__ void build_A(char* smraw, const float4* w0, int tid, int T) {
    float4 rel = d_rel[(size_t)T * 128 + tid];
    #pragma unroll
    for (int c = 0; c < 64; c += 4) {
        float h[4];
        #pragma unroll
        for (int u = 0; u < 4; u++) {
            float4 w = w0[c + u];
            h[u] = fmaxf(fmaf(w.z, rel.z, fmaf(w.y, rel.y, __fmul_rn(w.x, rel.x))) + w.w, 0.0f);
        }
        uint32_t h0, h1, l0, l1;
        split2(h[0], h[1], h0, l0); split2(h[2], h[3], h1, l1);
        uint32_t off = SWZ((uint32_t)(tid * 128 + c * 2));
        *(uint2*)(smraw + SM_AHI + off) = make_uint2(h0, h1);
        *(uint2*)(smraw + SM_ALO + off) = make_uint2(l0, l1);
    }
}
/* split MMA over K=64 for ONE m16 tile; full3 adds the a_lo*b_hi term */
__device__ __forceinline__ void mma_layer_mt(uint32_t smb, int rowbase, int lane,
                                             float acc[8][4], bool full3) {
    uint32_t rowA = rowbase + (lane & 15);
    uint32_t kbA  = (lane >> 4) * 8;
    uint32_t nB   = ((lane >> 4) * 8) + (lane & 7);
    uint32_t kbB  = ((lane >> 3) & 1) * 8;
    #pragma unroll
    for (int kt = 0; kt < 4; kt++) {
        uint32_t ah[4], al[4], bh[4][4], bl[4][4];
        uint32_t offa = SWZ(rowA*128 + (kbA + kt*16)*2);
        ldsm4(smb + SM_AHI + offa, ah);
        ldsm4(smb + SM_ALO + offa, al);
        #pragma unroll
        for (int u = 0; u < 4; u++) {
            uint32_t off = SWZ((nB + u*16)*128 + (kbB + kt*16)*2);
            ldsm4(smb + SM_BHI + off, bh[u]);
            ldsm4(smb + SM_BLO + off, bl[u]);
        }
        #pragma unroll
        for (int j = 0; j < 8; j++) {
            int u = j >> 1, h2 = (j & 1) * 2;
            mma_bf16(acc[j], ah, bh[u][h2], bh[u][h2+1]);
            mma_bf16(acc[j], ah, bl[u][h2], bl[u][h2+1]);
            if (full3) mma_bf16(acc[j], al, bh[u][h2], bh[u][h2+1]);
        }
    }
}

/* ------------------------- 4. GEMM-1: stats-only, 8 tiles/CTA ------------ */
__global__ __launch_bounds__(128, 3) void gemm1_kernel(const float* __restrict__ w2) {
    extern __shared__ char smraw[];
    uint32_t smb = smem_u32(smraw);
    float4* w0     = (float4*)(smraw + SM_W0);
    float*  wstats = (float*)(smraw + SM_STATS);
    int tid = threadIdx.x, wid = tid >> 5, lane = tid & 31;

    if (tid < 64) w0[tid] = d_w0eff[tid];
    build_B(smraw, w2, tid);

    float s0a[8], s1a[8], q0a[8], q1a[8];
    #pragma unroll
    for (int j = 0; j < 8; j++) { s0a[j] = s1a[j] = q0a[j] = q1a[j] = 0.0f; }

    for (int t = 0; t < TPC; t++) {
        __syncthreads();
        build_A(smraw, w0, tid, blockIdx.x * TPC + t);
        __syncthreads();

        #pragma unroll
        for (int mt = 0; mt < 2; mt++) {
            float acc[8][4];
            #pragma unroll
            for (int j = 0; j < 8; j++)
                #pragma unroll
                for (int v = 0; v < 4; v++) acc[j][v] = 0.0f;
            mma_layer_mt(smb, wid*32 + mt*16, lane, acc, false);  /* 2-term */
            #pragma unroll
            for (int j = 0; j < 8; j++) {
                s0a[j] += acc[j][0] + acc[j][2];
                s1a[j] += acc[j][1] + acc[j][3];
                q0a[j] += fmaf(acc[j][0], acc[j][0], acc[j][2]*acc[j][2]);
                q1a[j] += fmaf(acc[j][1], acc[j][1], acc[j][3]*acc[j][3]);
            }
        }
    }

    int q = lane & 3;
    #pragma unroll
    for (int j = 0; j < 8; j++) {
        float s0 = s0a[j], s1 = s1a[j], q0 = q0a[j], q1 = q1a[j];
        #pragma unroll
        for (int off = 4; off <= 16; off <<= 1) {
            s0 += __shfl_xor_sync(0xffffffffu, s0, off);
            s1 += __shfl_xor_sync(0xffffffffu, s1, off);
            q0 += __shfl_xor_sync(0xffffffffu, q0, off);
            q1 += __shfl_xor_sync(0xffffffffu, q1, off);
        }
        if (lane < 4) {
            int c0 = 8*j + 2*q;
            wstats[wid*128 + c0]          = s0;
            wstats[wid*128 + c0 + 1]      = s1;
            wstats[wid*128 + 64 + c0]     = q0;
            wstats[wid*128 + 64 + c0 + 1] = q1;
        }
    }
    __syncthreads();
    float a = wstats[tid] + wstats[128 + tid] + wstats[256 + tid] + wstats[384 + tid];
    d_z1stats[(size_t)blockIdx.x * 128 + tid] = a;
}

/* ------------------------- 5. fold BN-1 (two-stage reduce) --------------- */
__global__ __launch_bounds__(128) void statsA_kernel() {
    int t = threadIdx.x;
    int base = blockIdx.x * 8;
    double a = 0.0;
    for (int v = 0; v < 8; v++) a += (double)d_z1stats[(size_t)(base + v) * 128 + t];
    d_z1stats2[blockIdx.x * 128 + t] = a;
}

__global__ __launch_bounds__(128) void stats1_kernel(const float* __restrict__ gamma,
                                                     const float* __restrict__ beta) {
    __shared__ double S[128];
    int t = threadIdx.x;
    double acc = 0.0;
    #pragma unroll 8
    for (int c = 0; c < 64; c++) acc += d_z1stats2[c * 128 + t];
    S[t] = acc;
    __syncthreads();
    if (t < 64) {
        double mean = S[t] / (double)NCOL;
        double var  = S[64 + t] / (double)NCOL - mean * mean;
        float aa = gamma[t] * rsqrtf((float)var + 1e-5f);
        float cc = beta[t] - (float)mean * aa;
        d_a1c1[t] = make_float2(aa, cc);
    }
}

/* ------------------------- 6. GEMM-2: mt-sequential, fused epilogue ------ */
__global__ __launch_bounds__(128, 3) void gemm2_kernel(const float* __restrict__ w2,
                                                       const float* __restrict__ b2,
                                                       float* __restrict__ out) {
    extern __shared__ char smraw[];
    uint32_t smb = smem_u32(smraw);
    float4* w0    = (float4*)(smraw + SM_W0);
    float2* ac    = (float2*)(smraw + SM_AC);
    float*  sbias = (float*)(smraw + SM_BIAS);
    int tid = threadIdx.x, wid = tid >> 5, lane = tid & 31;

    if (tid < 64) { w0[tid] = d_w0eff[tid]; ac[tid] = d_a1c1[tid]; sbias[tid] = b2[tid]; }
    build_B(smraw, w2, tid);

    int q = lane & 3;
    uint32_t nB  = ((lane >> 4) * 8) + (lane & 7);
    uint32_t kbB = ((lane >> 3) & 1) * 8;

    for (int t = 0; t < TPC; t++) {
        int T = blockIdx.x * TPC + t;
        __syncthreads();
        build_A(smraw, w0, tid, T);
        __syncthreads();

        #pragma unroll
        for (int mt = 0; mt < 2; mt++) {
            /* layer-1 MMA (3-term) */
            float acc1[8][4];
            #pragma unroll
            for (int j = 0; j < 8; j++)
                #pragma unroll
                for (int v = 0; v < 4; v++) acc1[j][v] = 0.0f;
            mma_layer_mt(smb, wid*32 + mt*16, lane, acc1, true);

            /* BN-1 affine + relu + bf16-split: D-frags -> A-frags (in-lane) */
            uint32_t ahf[4][4], alf[4][4];
            #pragma unroll
            for (int kt = 0; kt < 4; kt++)
                #pragma unroll
                for (int half = 0; half < 2; half++) {
                    int j = 2*kt + half;
                    float2 c0 = ac[8*j + 2*q], c1 = ac[8*j + 2*q + 1];
                    float v0 = fmaxf(fmaf(c0.x, acc1[j][0], c0.y), 0.0f);
                    float v1 = fmaxf(fmaf(c1.x, acc1[j][1], c1.y), 0.0f);
                    float v2 = fmaxf(fmaf(c0.x, acc1[j][2], c0.y), 0.0f);
                    float v3 = fmaxf(fmaf(c1.x, acc1[j][3], c1.y), 0.0f);
                    split2(v0, v1, ahf[kt][half*2],     alf[kt][half*2]);
                    split2(v2, v3, ahf[kt][half*2 + 1], alf[kt][half*2 + 1]);
                }

            /* layer-2 MMA (3-term) */
            float acc2[8][4];
            #pragma unroll
            for (int j = 0; j < 8; j++)
                #pragma unroll
                for (int v = 0; v < 4; v++) acc2[j][v] = 0.0f;
            #pragma unroll
            for (int kt = 0; kt < 4; kt++) {
                uint32_t bh[4][4], bl[4][4];
                #pragma unroll
                for (int u = 0; u < 4; u++) {
                    uint32_t off = SWZ((nB + u*16)*128 + (kbB + kt*16)*2);
                    ldsm4(smb + SM_BHI + off, bh[u]);
                    ldsm4(smb + SM_BLO + off, bl[u]);
                }
                #pragma unroll
                for (int j = 0; j < 8; j++) {
                    int u = j >> 1, h2 = (j & 1) * 2;
                    mma_bf16(acc2[j], ahf[kt], bh[u][h2], bh[u][h2+1]);
                    mma_bf16(acc2[j], ahf[kt], bl[u][h2], bl[u][h2+1]);
                    mma_bf16(acc2[j], alf[kt], bh[u][h2], bh[u][h2+1]);
                }
            }

            /* max over this m16 tile (= one point's 16 neighbors) + bias */
            int g  = T * 8 + wid * 2 + mt;
            int bb = g >> 12, ii = g & 4095;
            #pragma unroll
            for (int j = 0; j < 8; j++) {
                float x = fmaxf(acc2[j][0], acc2[j][2]);
                float y = fmaxf(acc2[j][1], acc2[j][3]);
                #pragma unroll
                for (int off = 4; off <= 16; off <<= 1) {
                    x = fmaxf(x, __shfl_xor_sync(0xffffffffu, x, off));
                    y = fmaxf(y, __shfl_xor_sync(0xffffffffu, y, off));
                }
                if (lane < 4) {
                    int c0 = 8*j + 2*lane;
                    out[((size_t)(bb * CH + c0)     << 12) + ii] = x + sbias[c0];
                    out[((size_t)(bb * CH + c0 + 1) << 12) + ii] = y + sbias[c0 + 1];
                }
            }
        }
    }
}

/* ------------------------- launch ---------------------------------------- */
extern "C" void kernel_launch(void* const* d_in, const int* in_sizes, int n_in,
                              void* d_out, int out_size) {
    const float* xyz   = (const float*)d_in[0];
    const float* w1    = (const float*)d_in[1];
    const float* b1    = (const float*)d_in[2];
    const float* w2    = (const float*)d_in[3];
    const float* b2    = (const float*)d_in[4];
    const float* gamma = (const float*)d_in[5];
    const float* beta  = (const float*)d_in[6];
    float* out = (float*)d_out;

    cudaFuncSetAttribute(gemm1_kernel, cudaFuncAttributeMaxDynamicSharedMemorySize, SMEM_G);
    cudaFuncSetAttribute(gemm2_kernel, cudaFuncAttributeMaxDynamicSharedMemorySize, SMEM_G);

    bucket_kernel<<<BATCH, 1024>>>(xyz);
    knn_kernel<<<dim3(32, BATCH), 128>>>(xyz);
    prep_kernel<<<1, 64>>>(w1, b1, gamma, beta);
    gemm1_kernel<<<NGRID, 128, SMEM_G>>>(w2);
    statsA_kernel<<<64, 128>>>();
    stats1_kernel<<<1, 128>>>(gamma, beta);
    gemm2_kernel<<<NGRID, 128, SMEM_G>>>(w2, b2, out);
}

// round 11
// speedup vs baseline: 1.2889x; 1.2889x over previous
#include <cuda_runtime.h>
#include <cuda_fp16.h>
#include <cstdint>
#include <cstddef>

#define BATCH 8
#define NPT   4096
#define CH    64
#define NCOL  (BATCH*NPT*16)         /* 524288 columns */
#define NTIL  (NCOL/128)             /* 4096 tensor tiles */
#define TPC   2                      /* tiles per CTA */
#define NGRID (NTIL/TPC)             /* 2048 gemm CTAs */

/* ------------------------- device scratch (no allocs) ------------------- */
__device__ float4 d_psort[BATCH*NPT];
__device__ int    d_pidx [BATCH*NPT];
__device__ float4 d_rel  [NCOL];
__device__ float  d_relstats[256*9];
__device__ float4 d_w0eff[CH];
__device__ float  d_z1stats[(size_t)NGRID*128];
__device__ double d_z1stats2[64*128];
__device__ float2 d_a1c1[CH];

__device__ __forceinline__ float sq3(float x, float y, float z) {
    return __fadd_rn(__fadd_rn(__fmul_rn(x,x), __fmul_rn(y,y)), __fmul_rn(z,z));
}

/* ------------------------- warp-mma helpers (sm_80+ portable) ----------- */
__device__ __forceinline__ uint32_t smem_u32(const void* p) {
    uint32_t a;
    asm("{ .reg .u64 t; cvta.to.shared.u64 t, %1; cvt.u32.u64 %0, t; }" : "=r"(a) : "l"(p));
    return a;
}
#define SWZ(o) ((o) ^ (((o) >> 3) & 0x70))

__device__ __forceinline__ void ldsm4(uint32_t addr, uint32_t r[4]) {
    asm volatile("ldmatrix.sync.aligned.m8n8.x4.shared.b16 {%0,%1,%2,%3}, [%4];"
        : "=r"(r[0]), "=r"(r[1]), "=r"(r[2]), "=r"(r[3]) : "r"(addr));
}
__device__ __forceinline__ void mma_f16(float* c, const uint32_t* a,
                                        uint32_t b0, uint32_t b1) {
    asm volatile("mma.sync.aligned.m16n8k16.row.col.f32.f16.f16.f32 "
        "{%0,%1,%2,%3}, {%4,%5,%6,%7}, {%8,%9}, {%0,%1,%2,%3};"
        : "+f"(c[0]), "+f"(c[1]), "+f"(c[2]), "+f"(c[3])
        : "r"(a[0]), "r"(a[1]), "r"(a[2]), "r"(a[3]), "r"(b0), "r"(b1));
}
__device__ __forceinline__ uint32_t pkh(float a, float b) {
    __half2 h = __floats2half2_rn(a, b);
    return *(uint32_t*)&h;
}
/* split (a,b) into fp16 hi+lo packed pairs (a in low half) */
__device__ __forceinline__ void split2h(float a, float b, uint32_t& hi, uint32_t& lo) {
    __half ah = __float2half_rn(a), bh = __float2half_rn(b);
    float ar = a - __half2float(ah), br = b - __half2float(bh);
    hi = (uint32_t)__half_as_ushort(ah) | ((uint32_t)__half_as_ushort(bh) << 16);
    lo = pkh(ar, br);
}

/* smem layout (bytes): A = 128 cols x 128B (hi only), B = 64 ch x 128B x2 */
#define SM_AHI   0
#define SM_BHI   16384
#define SM_BLO   24576
#define SM_W0    32768
#define SM_STATS 33792
#define SM_AC    33792
#define SM_BIAS  35840
#define SMEM_G   36864

/* ------------------------- 1. bucket scatter (desc by |p|^2) ------------- */
/* 4096 buckets via top 13 bits (4 mantissa bits): within-bucket ratio 1.0625 */
__global__ __launch_bounds__(1024) void bucket_kernel(const float* __restrict__ xyz) {
    __shared__ int hist[4096];
    __shared__ int scan[4096];
    int b = blockIdx.x, tid = threadIdx.x;
    const float* xb = xyz + (size_t)b * 3 * NPT;

    #pragma unroll
    for (int s = 0; s < 4; s++) hist[tid + s*1024] = 0;
    __syncthreads();

    float xs[4], ys[4], zs[4], sqs[4];
    int bks[4];
    #pragma unroll
    for (int e = 0; e < 4; e++) {
        int i = e * 1024 + tid;
        float x = xb[i], y = xb[NPT + i], z = xb[2*NPT + i];
        float sq = sq3(x, y, z);
        unsigned int u = __float_as_uint(sq);
        int bk = 4095 - (int)(u >> 19);
        xs[e] = x; ys[e] = y; zs[e] = z; sqs[e] = sq; bks[e] = bk;
        atomicAdd(&hist[bk], 1);
    }
    __syncthreads();
    #pragma unroll
    for (int s = 0; s < 4; s++) scan[tid + s*1024] = hist[tid + s*1024];
    __syncthreads();
    for (int off = 1; off < 4096; off <<= 1) {
        int v[4];
        #pragma unroll
        for (int s = 0; s < 4; s++) {
            int idx = tid + s*1024;
            v[s] = (idx >= off) ? scan[idx - off] : 0;
        }
        __syncthreads();
        #pragma unroll
        for (int s = 0; s < 4; s++) scan[tid + s*1024] += v[s];
        __syncthreads();
    }
    #pragma unroll
    for (int s = 0; s < 4; s++) {
        int idx = tid + s*1024;
        hist[idx] = scan[idx] - hist[idx];   /* exclusive prefix as cursor */
    }
    __syncthreads();

    #pragma unroll
    for (int e = 0; e < 4; e++) {
        int pos = atomicAdd(&hist[bks[e]], 1);
        d_psort[(b << 12) + pos] = make_float4(xs[e], ys[e], zs[e], sqs[e]);
        d_pidx [(b << 12) + pos] = e * 1024 + tid;
    }
}

/* ------------------------- 2. kNN (farthest-16 after dropping rank 0) ---- */
__global__ __launch_bounds__(128) void knn_kernel(const float* __restrict__ xyz) {
    __shared__ float4 tP[512];
    __shared__ int    tI[512];
    __shared__ float  red[128];

    int b   = blockIdx.y;
    int tid = threadIdx.x;
    int i   = blockIdx.x * 128 + tid;
    const float* xb = xyz + (size_t)b * 3 * NPT;

    float px = xb[i], py = xb[NPT + i], pz = xb[2*NPT + i];
    float sqi  = sq3(px, py, pz);
    float si_r = sqrtf(sqi);

    unsigned long long heap[17];
    #pragma unroll
    for (int r = 0; r < 17; r++) heap[r] = 0ull;
    float thrF = __uint_as_float(0x7fffffffu);
    float B2   = -1.0f;
    bool  dead = false;

    for (int t0 = 0; t0 < NPT; t0 += 512) {
        for (int s = tid; s < 512; s += 128) {
            tP[s] = d_psort[(b << 12) + t0 + s];
            tI[s] = d_pidx [(b << 12) + t0 + s];
        }
        __syncthreads();
        if (!__all_sync(0xffffffffu, dead)) {
            #pragma unroll 4
            for (int u = 0; u < 512; u++) {
                if (!dead) {
                    float4 q = tP[u];
                    if (q.w < B2) dead = true;   /* B2 pre-scaled: bucket ratio 1.0625 */
                    else {
                        float dot = fmaf(pz, q.z, fmaf(py, q.y, __fmul_rn(px, q.x)));
                        float d   = __fsub_rn(__fadd_rn(sqi, q.w), __fmul_rn(2.0f, dot));
                        if (!(d < thrF)) {
                            int j2 = tI[u];
                            unsigned int bits = __float_as_uint(d);
                            unsigned int mono = bits ^ ((unsigned int)(((int)bits) >> 31) | 0x80000000u);
                            unsigned long long key =
                                ((unsigned long long)mono << 32) | (unsigned int)(~j2);
                            if (key > heap[16]) {
                                heap[16] = key;
                                #pragma unroll
                                for (int r = 16; r > 0; r--) {
                                    unsigned long long a_ = heap[r-1], c_ = heap[r];
                                    bool sw = c_ > a_;
                                    heap[r-1] = sw ? c_ : a_;
                                    heap[r]   = sw ? a_ : c_;
                                }
                                unsigned int h16 = (unsigned int)(heap[16] >> 32);
                                thrF = __uint_as_float((h16 & 0x80000000u) ? (h16 ^ 0x80000000u)
                                                                           : ~h16);
                                float L   = __fmaf_rn(-1e-4f, thrF, thrF) - 1e-6f;
                                float sL  = sqrtf(L);
                                float bb2 = sL - si_r;
                                B2 = (bb2 > 0.0f) ? bb2 * bb2 * 0.9412f : -1.0f;
                            }
                        }
                    }
                }
                if ((u & 31) == 31 && __all_sync(0xffffffffu, dead)) break;
            }
        }
        if (__syncthreads_and(dead)) break;
    }

    float sx=0,sy=0,sz=0,sxx=0,syy=0,szz=0,sxy=0,sxz=0,syz=0;
    size_t base = ((size_t)((b << 12) + i)) << 4;
    #pragma unroll
    for (int r = 1; r < 17; r++) {
        int j2 = ~((unsigned int)heap[r]);
        float rx = __fsub_rn(xb[j2],         px);
        float ry = __fsub_rn(xb[NPT  + j2],  py);
        float rz = __fsub_rn(xb[2*NPT + j2], pz);
        d_rel[base + (r - 1)] = make_float4(rx, ry, rz, 0.0f);
        sx += rx; sy += ry; sz += rz;
        sxx = fmaf(rx, rx, sxx); syy = fmaf(ry, ry, syy); szz = fmaf(rz, rz, szz);
        sxy = fmaf(rx, ry, sxy); sxz = fmaf(rx, rz, sxz); syz = fmaf(ry, rz, syz);
    }
    float st[9] = {sx, sy, sz, sxx, syy, szz, sxy, sxz, syz};
    int blk = b * 32 + blockIdx.x;
    for (int s = 0; s < 9; s++) {
        __syncthreads();
        red[tid] = st[s];
        __syncthreads();
        for (int off = 64; off; off >>= 1) {
            if (tid < off) red[tid] += red[tid + off];
            __syncthreads();
        }
        if (tid == 0) d_relstats[blk * 9 + s] = red[0];
    }
}

/* ------------------------- 3. fold block-0 conv+BN+relu ------------------ */
__global__ __launch_bounds__(64) void prep_kernel(const float* __restrict__ w1,
                                                  const float* __restrict__ b1,
                                                  const float* __restrict__ gamma,
                                                  const float* __restrict__ beta) {
    __shared__ double S[9];
    int t = threadIdx.x;
    if (t < 9) {
        double acc = 0.0;
        for (int v = 0; v < 256; v++) acc += (double)d_relstats[v * 9 + t];
        S[t] = acc;
    }
    __syncthreads();
    double inv = 1.0 / (double)NCOL;
    double mx = S[0]*inv, my = S[1]*inv, mz = S[2]*inv;
    double cxx = S[3]*inv - mx*mx, cyy = S[4]*inv - my*my, czz = S[5]*inv - mz*mz;
    double cxy = S[6]*inv - mx*my, cxz = S[7]*inv - mx*mz, cyz = S[8]*inv - my*mz;
    double wx = w1[t*3], wy = w1[t*3+1], wz = w1[t*3+2];
    double var = wx*(wx*cxx + 2.0*(wy*cxy + wz*cxz)) + wy*(wy*cyy + 2.0*wz*cyz) + wz*wz*czz;
    double mu  = wx*mx + wy*my + wz*mz + (double)b1[t];
    float aa = gamma[t] * rsqrtf((float)var + 1e-5f);
    float cc = beta[t] - (float)mu * aa;
    d_w0eff[t] = make_float4(aa*(float)wx, aa*(float)wy, aa*(float)wz, fmaf(aa, b1[t], cc));
}

/* -------- shared device code ------------------------------------------- */
__device__ __forceinline__ void build_B(char* smraw, const float* __restrict__ w2, int tid) {
    int n = tid >> 1, k0 = (tid & 1) * 32;
    const float* wrow = w2 + n * 64 + k0;
    #pragma unroll
    for (int k = 0; k < 32; k += 4) {
        float4 v = *(const float4*)(wrow + k);
        uint32_t h0, h1, l0, l1;
        split2h(v.x, v.y, h0, l0); split2h(v.z, v.w, h1, l1);
        uint32_t off = SWZ((uint32_t)(n * 128 + (k0 + k) * 2));
        *(uint2*)(smraw + SM_BHI + off) = make_uint2(h0, h1);
        *(uint2*)(smraw + SM_BLO + off) = make_uint2(l0, l1);
    }
}
/* A = h0 in fp16, hi only */
__device__ __forceinline__ void build_A(char* smraw, const float4* w0, int tid, int T) {
    float4 rel = d_rel[(size_t)T * 128 + tid];
    #pragma unroll
    for (int c = 0; c < 64; c += 4) {
        float h[4];
        #pragma unroll
        for (int u = 0; u < 4; u++) {
            float4 w = w0[c + u];
            h[u] = fmaxf(fmaf(w.z, rel.z, fmaf(w.y, rel.y, __fmul_rn(w.x, rel.x))) + w.w, 0.0f);
        }
        uint32_t off = SWZ((uint32_t)(tid * 128 + c * 2));
        *(uint2*)(smraw + SM_AHI + off) = make_uint2(pkh(h[0], h[1]), pkh(h[2], h[3]));
    }
}
/* 2-term MMA over K=64 for ONE m16 tile: A(hi) x (Bhi + Blo) */
__device__ __forceinline__ void mma_layer_hi(uint32_t smb, int rowbase, int lane,
                                             float acc[8][4]) {
    uint32_t rowA = rowbase + (lane & 15);
    uint32_t kbA  = (lane >> 4) * 8;
    uint32_t nB   = ((lane >> 4) * 8) + (lane & 7);
    uint32_t kbB  = ((lane >> 3) & 1) * 8;
    #pragma unroll
    for (int kt = 0; kt < 4; kt++) {
        uint32_t ah[4], bh[4][4], bl[4][4];
        ldsm4(smb + SM_AHI + SWZ(rowA*128 + (kbA + kt*16)*2), ah);
        #pragma unroll
        for (int u = 0; u < 4; u++) {
            uint32_t off = SWZ((nB + u*16)*128 + (kbB + kt*16)*2);
            ldsm4(smb + SM_BHI + off, bh[u]);
            ldsm4(smb + SM_BLO + off, bl[u]);
        }
        #pragma unroll
        for (int j = 0; j < 8; j++) {
            int u = j >> 1, h2 = (j & 1) * 2;
            mma_f16(acc[j], ah, bh[u][h2], bh[u][h2+1]);
            mma_f16(acc[j], ah, bl[u][h2], bl[u][h2+1]);
        }
    }
}

/* ------------------------- 4. GEMM-1: stats-only, 2 tiles/CTA ------------ */
__global__ __launch_bounds__(128, 4) void gemm1_kernel(const float* __restrict__ w2) {
    extern __shared__ char smraw[];
    uint32_t smb = smem_u32(smraw);
    float4* w0     = (float4*)(smraw + SM_W0);
    float*  wstats = (float*)(smraw + SM_STATS);
    int tid = threadIdx.x, wid = tid >> 5, lane = tid & 31;

    if (tid < 64) w0[tid] = d_w0eff[tid];
    build_B(smraw, w2, tid);

    float s0a[8], s1a[8], q0a[8], q1a[8];
    #pragma unroll
    for (int j = 0; j < 8; j++) { s0a[j] = s1a[j] = q0a[j] = q1a[j] = 0.0f; }

    for (int t = 0; t < TPC; t++) {
        __syncthreads();
        build_A(smraw, w0, tid, blockIdx.x * TPC + t);
        __syncthreads();

        #pragma unroll
        for (int mt = 0; mt < 2; mt++) {
            float acc[8][4];
            #pragma unroll
            for (int j = 0; j < 8; j++)
                #pragma unroll
                for (int v = 0; v < 4; v++) acc[j][v] = 0.0f;
            mma_layer_hi(smb, wid*32 + mt*16, lane, acc);
            #pragma unroll
            for (int j = 0; j < 8; j++) {
                s0a[j] += acc[j][0] + acc[j][2];
                s1a[j] += acc[j][1] + acc[j][3];
                q0a[j] += fmaf(acc[j][0], acc[j][0], acc[j][2]*acc[j][2]);
                q1a[j] += fmaf(acc[j][1], acc[j][1], acc[j][3]*acc[j][3]);
            }
        }
    }

    int q = lane & 3;
    #pragma unroll
    for (int j = 0; j < 8; j++) {
        float s0 = s0a[j], s1 = s1a[j], q0 = q0a[j], q1 = q1a[j];
        #pragma unroll
        for (int off = 4; off <= 16; off <<= 1) {
            s0 += __shfl_xor_sync(0xffffffffu, s0, off);
            s1 += __shfl_xor_sync(0xffffffffu, s1, off);
            q0 += __shfl_xor_sync(0xffffffffu, q0, off);
            q1 += __shfl_xor_sync(0xffffffffu, q1, off);
        }
        if (lane < 4) {
            int c0 = 8*j + 2*q;
            wstats[wid*128 + c0]          = s0;
            wstats[wid*128 + c0 + 1]      = s1;
            wstats[wid*128 + 64 + c0]     = q0;
            wstats[wid*128 + 64 + c0 + 1] = q1;
        }
    }
    __syncthreads();
    float a = wstats[tid] + wstats[128 + tid] + wstats[256 + tid] + wstats[384 + tid];
    d_z1stats[(size_t)blockIdx.x * 128 + tid] = a;
}

/* ------------------------- 5. fold BN-1 (two-stage reduce) --------------- */
__global__ __launch_bounds__(128) void statsA_kernel() {
    int t = threadIdx.x;
    int base = blockIdx.x * 32;
    double a = 0.0;
    for (int v = 0; v < 32; v++) a += (double)d_z1stats[(size_t)(base + v) * 128 + t];
    d_z1stats2[blockIdx.x * 128 + t] = a;
}

__global__ __launch_bounds__(128) void stats1_kernel(const float* __restrict__ gamma,
                                                     const float* __restrict__ beta) {
    __shared__ double S[128];
    int t = threadIdx.x;
    double acc = 0.0;
    #pragma unroll 8
    for (int c = 0; c < 64; c++) acc += d_z1stats2[c * 128 + t];
    S[t] = acc;
    __syncthreads();
    if (t < 64) {
        double mean = S[t] / (double)NCOL;
        double var  = S[64 + t] / (double)NCOL - mean * mean;
        float aa = gamma[t] * rsqrtf((float)var + 1e-5f);
        float cc = beta[t] - (float)mean * aa;
        d_a1c1[t] = make_float2(aa, cc);
    }
}

/* ------------------------- 6. GEMM-2: 2 tiles/CTA, fused epilogue -------- */
__global__ __launch_bounds__(128, 3) void gemm2_kernel(const float* __restrict__ w2,
                                                       const float* __restrict__ b2,
                                                       float* __restrict__ out) {
    extern __shared__ char smraw[];
    uint32_t smb = smem_u32(smraw);
    float4* w0    = (float4*)(smraw + SM_W0);
    float2* ac    = (float2*)(smraw + SM_AC);
    float*  sbias = (float*)(smraw + SM_BIAS);
    int tid = threadIdx.x, wid = tid >> 5, lane = tid & 31;

    if (tid < 64) { w0[tid] = d_w0eff[tid]; ac[tid] = d_a1c1[tid]; sbias[tid] = b2[tid]; }
    build_B(smraw, w2, tid);

    int q = lane & 3;
    uint32_t nB  = ((lane >> 4) * 8) + (lane & 7);
    uint32_t kbB = ((lane >> 3) & 1) * 8;

    for (int t = 0; t < TPC; t++) {
        int T = blockIdx.x * TPC + t;
        __syncthreads();
        build_A(smraw, w0, tid, T);
        __syncthreads();

        #pragma unroll
        for (int mt = 0; mt < 2; mt++) {
            /* layer-1 MMA (2-term fp16) — arithmetic identical to gemm1 */
            float acc1[8][4];
            #pragma unroll
            for (int j = 0; j < 8; j++)
                #pragma unroll
                for (int v = 0; v < 4; v++) acc1[j][v] = 0.0f;
            mma_layer_hi(smb, wid*32 + mt*16, lane, acc1);

            /* BN-1 affine + relu + fp16 pack: D-frags -> A-frags (in-lane) */
            uint32_t ahf[4][4];
            #pragma unroll
            for (int kt = 0; kt < 4; kt++)
                #pragma unroll
                for (int half = 0; half < 2; half++) {
                    int j = 2*kt + half;
                    float2 c0 = ac[8*j + 2*q], c1 = ac[8*j + 2*q + 1];
                    float v0 = fmaxf(fmaf(c0.x, acc1[j][0], c0.y), 0.0f);
                    float v1 = fmaxf(fmaf(c1.x, acc1[j][1], c1.y), 0.0f);
                    float v2 = fmaxf(fmaf(c0.x, acc1[j][2], c0.y), 0.0f);
                    float v3 = fmaxf(fmaf(c1.x, acc1[j][3], c1.y), 0.0f);
                    ahf[kt][half*2]     = pkh(v0, v1);
                    ahf[kt][half*2 + 1] = pkh(v2, v3);
                }

            /* layer-2 MMA (2-term fp16) */
            float acc2[8][4];
            #pragma unroll
            for (int j = 0; j < 8; j++)
                #pragma unroll
                for (int v = 0; v < 4; v++) acc2[j][v] = 0.0f;
            #pragma unroll
            for (int kt = 0; kt < 4; kt++) {
                uint32_t bh[4][4], bl[4][4];
                #pragma unroll
                for (int u = 0; u < 4; u++) {
                    uint32_t off = SWZ((nB + u*16)*128 + (kbB + kt*16)*2);
                    ldsm4(smb + SM_BHI + off, bh[u]);
                    ldsm4(smb + SM_BLO + off, bl[u]);
                }
                #pragma unroll
                for (int j = 0; j < 8; j++) {
                    int u = j >> 1, h2 = (j & 1) * 2;
                    mma_f16(acc2[j], ahf[kt], bh[u][h2], bh[u][h2+1]);
                    mma_f16(acc2[j], ahf[kt], bl[u][h2], bl[u][h2+1]);
                }
            }

            /* max over this m16 tile (= one point's 16 neighbors) + bias */
            int g  = T * 8 + wid * 2 + mt;
            int bb = g >> 12, ii = g & 4095;
            #pragma unroll
            for (int j = 0; j < 8; j++) {
                float x = fmaxf(acc2[j][0], acc2[j][2]);
                float y = fmaxf(acc2[j][1], acc2[j][3]);
                #pragma unroll
                for (int off = 4; off <= 16; off <<= 1) {
                    x = fmaxf(x, __shfl_xor_sync(0xffffffffu, x, off));
                    y = fmaxf(y, __shfl_xor_sync(0xffffffffu, y, off));
                }
                if (lane < 4) {
                    int c0 = 8*j + 2*lane;
                    out[((size_t)(bb * CH + c0)     << 12) + ii] = x + sbias[c0];
                    out[((size_t)(bb * CH + c0 + 1) << 12) + ii] = y + sbias[c0 + 1];
                }
            }
        }
    }
}

/* ------------------------- launch ---------------------------------------- */
extern "C" void kernel_launch(void* const* d_in, const int* in_sizes, int n_in,
                              void* d_out, int out_size) {
    const float* xyz   = (const float*)d_in[0];
    const float* w1    = (const float*)d_in[1];
    const float* b1    = (const float*)d_in[2];
    const float* w2    = (const float*)d_in[3];
    const float* b2    = (const float*)d_in[4];
    const float* gamma = (const float*)d_in[5];
    const float* beta  = (const float*)d_in[6];
    float* out = (float*)d_out;

    cudaFuncSetAttribute(gemm1_kernel, cudaFuncAttributeMaxDynamicSharedMemorySize, SMEM_G);
    cudaFuncSetAttribute(gemm2_kernel, cudaFuncAttributeMaxDynamicSharedMemorySize, SMEM_G);

    bucket_kernel<<<BATCH, 1024>>>(xyz);
    knn_kernel<<<dim3(32, BATCH), 128>>>(xyz);
    prep_kernel<<<1, 64>>>(w1, b1, gamma, beta);
    gemm1_kernel<<<NGRID, 128, SMEM_G>>>(w2);
    statsA_kernel<<<64, 128>>>();
    stats1_kernel<<<1, 128>>>(gamma, beta);
    gemm2_kernel<<<NGRID, 128, SMEM_G>>>(w2, b2, out);
}

// round 13
// speedup vs baseline: 1.4407x; 1.1178x over previous
#include <cuda_runtime.h>
#include <cuda_fp16.h>
#include <cstdint>
#include <cstddef>

#define BATCH 8
#define NPT   4096
#define CH    64
#define NCOL  (BATCH*NPT*16)         /* 524288 columns */
#define NTIL  (NCOL/128)             /* 4096 tensor tiles */
#define TPC   2                      /* tiles per CTA */
#define NGRID (NTIL/TPC)             /* 2048 gemm CTAs */

/* ------------------------- device scratch (no allocs) ------------------- */
__device__ float4 d_psort[BATCH*NPT];
__device__ int    d_pidx [BATCH*NPT];
__device__ float4 d_rel  [NCOL];
__device__ float  d_relstats[256*9];
__device__ float4 d_w0eff[CH];
__device__ float  d_z1stats[(size_t)NGRID*128];
__device__ double d_z1stats2[64*128];
__device__ float2 d_a1c1[CH];
__device__ uint2  d_z1h[(size_t)NTIL*2048];   /* 64 MiB: fp16 z1 fragments */

__device__ __forceinline__ float sq3(float x, float y, float z) {
    return __fadd_rn(__fadd_rn(__fmul_rn(x,x), __fmul_rn(y,y)), __fmul_rn(z,z));
}

/* ------------------------- warp-mma helpers (sm_80+ portable) ----------- */
__device__ __forceinline__ uint32_t smem_u32(const void* p) {
    uint32_t a;
    asm("{ .reg .u64 t; cvta.to.shared.u64 t, %1; cvt.u32.u64 %0, t; }" : "=r"(a) : "l"(p));
    return a;
}
#define SWZ(o) ((o) ^ (((o) >> 3) & 0x70))

__device__ __forceinline__ void ldsm4(uint32_t addr, uint32_t r[4]) {
    asm volatile("ldmatrix.sync.aligned.m8n8.x4.shared.b16 {%0,%1,%2,%3}, [%4];"
        : "=r"(r[0]), "=r"(r[1]), "=r"(r[2]), "=r"(r[3]) : "r"(addr));
}
__device__ __forceinline__ void mma_f16(float* c, const uint32_t* a,
                                        uint32_t b0, uint32_t b1) {
    asm volatile("mma.sync.aligned.m16n8k16.row.col.f32.f16.f16.f32 "
        "{%0,%1,%2,%3}, {%4,%5,%6,%7}, {%8,%9}, {%0,%1,%2,%3};"
        : "+f"(c[0]), "+f"(c[1]), "+f"(c[2]), "+f"(c[3])
        : "r"(a[0]), "r"(a[1]), "r"(a[2]), "r"(a[3]), "r"(b0), "r"(b1));
}
__device__ __forceinline__ uint32_t pkh(float a, float b) {
    __half2 h = __floats2half2_rn(a, b);
    return *(uint32_t*)&h;
}
__device__ __forceinline__ void split2h(float a, float b, uint32_t& hi, uint32_t& lo) {
    __half ah = __float2half_rn(a), bh = __float2half_rn(b);
    float ar = a - __half2float(ah), br = b - __half2float(bh);
    hi = (uint32_t)__half_as_ushort(ah) | ((uint32_t)__half_as_ushort(bh) << 16);
    lo = pkh(ar, br);
}

/* gemm1 smem layout (bytes) */
#define SM_AHI   0
#define SM_BHI   16384
#define SM_BLO   24576
#define SM_W0    32768
#define SM_STATS 33792
#define SMEM_G   36864
/* gemm2 smem layout (bytes) */
#define SM2_BHI  0
#define SM2_BLO  8192
#define SM2_AC   16384
#define SM2_BIAS 16896
#define SMEM_G2  17408

/* ------------------------- 1. bucket scatter (desc by |p|^2) ------------- */
__global__ __launch_bounds__(1024) void bucket_kernel(const float* __restrict__ xyz) {
    __shared__ int hist[4096];
    __shared__ int scan[4096];
    int b = blockIdx.x, tid = threadIdx.x;
    const float* xb = xyz + (size_t)b * 3 * NPT;

    #pragma unroll
    for (int s = 0; s < 4; s++) hist[tid + s*1024] = 0;
    __syncthreads();

    float xs[4], ys[4], zs[4], sqs[4];
    int bks[4];
    #pragma unroll
    for (int e = 0; e < 4; e++) {
        int i = e * 1024 + tid;
        float x = xb[i], y = xb[NPT + i], z = xb[2*NPT + i];
        float sq = sq3(x, y, z);
        unsigned int u = __float_as_uint(sq);
        int bk = 4095 - (int)(u >> 19);
        xs[e] = x; ys[e] = y; zs[e] = z; sqs[e] = sq; bks[e] = bk;
        atomicAdd(&hist[bk], 1);
    }
    __syncthreads();
    #pragma unroll
    for (int s = 0; s < 4; s++) scan[tid + s*1024] = hist[tid + s*1024];
    __syncthreads();
    for (int off = 1; off < 4096; off <<= 1) {
        int v[4];
        #pragma unroll
        for (int s = 0; s < 4; s++) {
            int idx = tid + s*1024;
            v[s] = (idx >= off) ? scan[idx - off] : 0;
        }
        __syncthreads();
        #pragma unroll
        for (int s = 0; s < 4; s++) scan[tid + s*1024] += v[s];
        __syncthreads();
    }
    #pragma unroll
    for (int s = 0; s < 4; s++) {
        int idx = tid + s*1024;
        hist[idx] = scan[idx] - hist[idx];
    }
    __syncthreads();

    #pragma unroll
    for (int e = 0; e < 4; e++) {
        int pos = atomicAdd(&hist[bks[e]], 1);
        d_psort[(b << 12) + pos] = make_float4(xs[e], ys[e], zs[e], sqs[e]);
        d_pidx [(b << 12) + pos] = e * 1024 + tid;
    }
}

/* ------------------------- 2. kNN (farthest-16 after dropping rank 0) ---- */
__global__ __launch_bounds__(128) void knn_kernel(const float* __restrict__ xyz) {
    __shared__ float4 tP[512];
    __shared__ int    tI[512];
    __shared__ float  red[128];

    int b   = blockIdx.y;
    int tid = threadIdx.x;
    int i   = blockIdx.x * 128 + tid;
    const float* xb = xyz + (size_t)b * 3 * NPT;

    float px = xb[i], py = xb[NPT + i], pz = xb[2*NPT + i];
    float sqi  = sq3(px, py, pz);
    float si_r = sqrtf(sqi);

    unsigned long long heap[17];
    #pragma unroll
    for (int r = 0; r < 17; r++) heap[r] = 0ull;
    float thrF = __uint_as_float(0x7fffffffu);
    float B2   = -1.0f;
    bool  dead = false;

    for (int t0 = 0; t0 < NPT; t0 += 512) {
        for (int s = tid; s < 512; s += 128) {
            tP[s] = d_psort[(b << 12) + t0 + s];
            tI[s] = d_pidx [(b << 12) + t0 + s];
        }
        __syncthreads();
        if (!__all_sync(0xffffffffu, dead)) {
            #pragma unroll 4
            for (int u = 0; u < 512; u++) {
                if (!dead) {
                    float4 q = tP[u];
                    if (q.w < B2) dead = true;
                    else {
                        float dot = fmaf(pz, q.z, fmaf(py, q.y, __fmul_rn(px, q.x)));
                        float d   = __fsub_rn(__fadd_rn(sqi, q.w), __fmul_rn(2.0f, dot));
                        if (!(d < thrF)) {
                            int j2 = tI[u];
                            unsigned int bits = __float_as_uint(d);
                            unsigned int mono = bits ^ ((unsigned int)(((int)bits) >> 31) | 0x80000000u);
                            unsigned long long key =
                                ((unsigned long long)mono << 32) | (unsigned int)(~j2);
                            if (key > heap[16]) {
                                heap[16] = key;
                                #pragma unroll
                                for (int r = 16; r > 0; r--) {
                                    unsigned long long a_ = heap[r-1], c_ = heap[r];
                                    bool sw = c_ > a_;
                                    heap[r-1] = sw ? c_ : a_;
                                    heap[r]   = sw ? a_ : c_;
                                }
                                unsigned int h16 = (unsigned int)(heap[16] >> 32);
                                thrF = __uint_as_float((h16 & 0x80000000u) ? (h16 ^ 0x80000000u)
                                                                           : ~h16);
                                float L   = __fmaf_rn(-1e-4f, thrF, thrF) - 1e-6f;
                                float sL  = sqrtf(L);
                                float bb2 = sL - si_r;
                                B2 = (bb2 > 0.0f) ? bb2 * bb2 * 0.9412f : -1.0f;
                            }
                        }
                    }
                }
                if ((u & 31) == 31 && __all_sync(0xffffffffu, dead)) break;
            }
        }
        if (__syncthreads_and(dead)) break;
    }

    float sx=0,sy=0,sz=0,sxx=0,syy=0,szz=0,sxy=0,sxz=0,syz=0;
    size_t base = ((size_t)((b << 12) + i)) << 4;
    #pragma unroll
    for (int r = 1; r < 17; r++) {
        int j2 = ~((unsigned int)heap[r]);
        float rx = __fsub_rn(xb[j2],         px);
        float ry = __fsub_rn(xb[NPT  + j2],  py);
        float rz = __fsub_rn(xb[2*NPT + j2], pz);
        d_rel[base + (r - 1)] = make_float4(rx, ry, rz, 0.0f);
        sx += rx; sy += ry; sz += rz;
        sxx = fmaf(rx, rx, sxx); syy = fmaf(ry, ry, syy); szz = fmaf(rz, rz, szz);
        sxy = fmaf(rx, ry, sxy); sxz = fmaf(rx, rz, sxz); syz = fmaf(ry, rz, syz);
    }
    float st[9] = {sx, sy, sz, sxx, syy, szz, sxy, sxz, syz};
    int blk = b * 32 + blockIdx.x;
    for (int s = 0; s < 9; s++) {
        __syncthreads();
        red[tid] = st[s];
        __syncthreads();
        for (int off = 64; off; off >>= 1) {
            if (tid < off) red[tid] += red[tid + off];
            __syncthreads();
        }
        if (tid == 0) d_relstats[blk * 9 + s] = red[0];
    }
}

/* ------------------------- 3. fold block-0 conv+BN+relu ------------------ */
__global__ __launch_bounds__(64) void prep_kernel(const float* __restrict__ w1,
                                                  const float* __restrict__ b1,
                                                  const float* __restrict__ gamma,
                                                  const float* __restrict__ beta) {
    __shared__ double S[9];
    int t = threadIdx.x;
    if (t < 9) {
        double acc = 0.0;
        for (int v = 0; v < 256; v++) acc += (double)d_relstats[v * 9 + t];
        S[t] = acc;
    }
    __syncthreads();
    double inv = 1.0 / (double)NCOL;
    double mx = S[0]*inv, my = S[1]*inv, mz = S[2]*inv;
    double cxx = S[3]*inv - mx*mx, cyy = S[4]*inv - my*my, czz = S[5]*inv - mz*mz;
    double cxy = S[6]*inv - mx*my, cxz = S[7]*inv - mx*mz, cyz = S[8]*inv - my*mz;
    double wx = w1[t*3], wy = w1[t*3+1], wz = w1[t*3+2];
    double var = wx*(wx*cxx + 2.0*(wy*cxy + wz*cxz)) + wy*(wy*cyy + 2.0*wz*cyz) + wz*wz*czz;
    double mu  = wx*mx + wy*my + wz*mz + (double)b1[t];
    float aa = gamma[t] * rsqrtf((float)var + 1e-5f);
    float cc = beta[t] - (float)mu * aa;
    d_w0eff[t] = make_float4(aa*(float)wx, aa*(float)wy, aa*(float)wz, fmaf(aa, b1[t], cc));
}

/* -------- shared device code ------------------------------------------- */
__device__ __forceinline__ void build_B(char* smraw, int bhi, int blo,
                                        const float* __restrict__ w2, int tid) {
    int n = tid >> 1, k0 = (tid & 1) * 32;
    const float* wrow = w2 + n * 64 + k0;
    #pragma unroll
    for (int k = 0; k < 32; k += 4) {
        float4 v = *(const float4*)(wrow + k);
        uint32_t h0, h1, l0, l1;
        split2h(v.x, v.y, h0, l0); split2h(v.z, v.w, h1, l1);
        uint32_t off = SWZ((uint32_t)(n * 128 + (k0 + k) * 2));
        *(uint2*)(smraw + bhi + off) = make_uint2(h0, h1);
        *(uint2*)(smraw + blo + off) = make_uint2(l0, l1);
    }
}
__device__ __forceinline__ void build_A(char* smraw, const float4* w0, int tid, int T) {
    float4 rel = d_rel[(size_t)T * 128 + tid];
    #pragma unroll
    for (int c = 0; c < 64; c += 4) {
        float h[4];
        #pragma unroll
        for (int u = 0; u < 4; u++) {
            float4 w = w0[c + u];
            h[u] = fmaxf(fmaf(w.z, rel.z, fmaf(w.y, rel.y, __fmul_rn(w.x, rel.x))) + w.w, 0.0f);
        }
        uint32_t off = SWZ((uint32_t)(tid * 128 + c * 2));
        *(uint2*)(smraw + SM_AHI + off) = make_uint2(pkh(h[0], h[1]), pkh(h[2], h[3]));
    }
}
/* 2-term MMA over K=64 for ONE m16 tile: A(hi) x (Bhi + Blo) */
__device__ __forceinline__ void mma_layer_hi(uint32_t smb, int rowbase, int lane,
                                             float acc[8][4]) {
    uint32_t rowA = rowbase + (lane & 15);
    uint32_t kbA  = (lane >> 4) * 8;
    uint32_t nB   = ((lane >> 4) * 8) + (lane & 7);
    uint32_t kbB  = ((lane >> 3) & 1) * 8;
    #pragma unroll
    for (int kt = 0; kt < 4; kt++) {
        uint32_t ah[4], bh[4][4], bl[4][4];
        ldsm4(smb + SM_AHI + SWZ(rowA*128 + (kbA + kt*16)*2), ah);
        #pragma unroll
        for (int u = 0; u < 4; u++) {
            uint32_t off = SWZ((nB + u*16)*128 + (kbB + kt*16)*2);
            ldsm4(smb + SM_BHI + off, bh[u]);
            ldsm4(smb + SM_BLO + off, bl[u]);
        }
        #pragma unroll
        for (int j = 0; j < 8; j++) {
            int u = j >> 1, h2 = (j & 1) * 2;
            mma_f16(acc[j], ah, bh[u][h2], bh[u][h2+1]);
            mma_f16(acc[j], ah, bl[u][h2], bl[u][h2+1]);
        }
    }
}

/* ------------------------- 4. GEMM-1: z1-fp16 dump + stats --------------- */
__global__ __launch_bounds__(128, 4) void gemm1_kernel(const float* __restrict__ w2) {
    extern __shared__ char smraw[];
    uint32_t smb = smem_u32(smraw);
    float4* w0     = (float4*)(smraw + SM_W0);
    float*  wstats = (float*)(smraw + SM_STATS);
    int tid = threadIdx.x, wid = tid >> 5, lane = tid & 31;

    if (tid < 64) w0[tid] = d_w0eff[tid];
    build_B(smraw, SM_BHI, SM_BLO, w2, tid);

    float s0a[8], s1a[8], q0a[8], q1a[8];
    #pragma unroll
    for (int j = 0; j < 8; j++) { s0a[j] = s1a[j] = q0a[j] = q1a[j] = 0.0f; }

    for (int t = 0; t < TPC; t++) {
        int T = blockIdx.x * TPC + t;
        __syncthreads();
        build_A(smraw, w0, tid, T);
        __syncthreads();

        #pragma unroll
        for (int mt = 0; mt < 2; mt++) {
            float acc[8][4];
            #pragma unroll
            for (int j = 0; j < 8; j++)
                #pragma unroll
                for (int v = 0; v < 4; v++) acc[j][v] = 0.0f;
            mma_layer_hi(smb, wid*32 + mt*16, lane, acc);

            /* dump fragments as fp16 (coalesced 256B per j per warp) */
            size_t zb = ((((size_t)T*4 + wid)*2 + mt)*8)*32 + lane;
            #pragma unroll
            for (int j = 0; j < 8; j++)
                d_z1h[zb + (size_t)j*32] =
                    make_uint2(pkh(acc[j][0], acc[j][1]), pkh(acc[j][2], acc[j][3]));

            #pragma unroll
            for (int j = 0; j < 8; j++) {
                s0a[j] += acc[j][0] + acc[j][2];
                s1a[j] += acc[j][1] + acc[j][3];
                q0a[j] += fmaf(acc[j][0], acc[j][0], acc[j][2]*acc[j][2]);
                q1a[j] += fmaf(acc[j][1], acc[j][1], acc[j][3]*acc[j][3]);
            }
        }
    }

    int q = lane & 3;
    #pragma unroll
    for (int j = 0; j < 8; j++) {
        float s0 = s0a[j], s1 = s1a[j], q0 = q0a[j], q1 = q1a[j];
        #pragma unroll
        for (int off = 4; off <= 16; off <<= 1) {
            s0 += __shfl_xor_sync(0xffffffffu, s0, off);
            s1 += __shfl_xor_sync(0xffffffffu, s1, off);
            q0 += __shfl_xor_sync(0xffffffffu, q0, off);
            q1 += __shfl_xor_sync(0xffffffffu, q1, off);
        }
        if (lane < 4) {
            int c0 = 8*j + 2*q;
            wstats[wid*128 + c0]          = s0;
            wstats[wid*128 + c0 + 1]      = s1;
            wstats[wid*128 + 64 + c0]     = q0;
            wstats[wid*128 + 64 + c0 + 1] = q1;
        }
    }
    __syncthreads();
    float a = wstats[tid] + wstats[128 + tid] + wstats[256 + tid] + wstats[384 + tid];
    d_z1stats[(size_t)blockIdx.x * 128 + tid] = a;
}

/* ------------------------- 5. fold BN-1 (two-stage reduce) --------------- */
__global__ __launch_bounds__(128) void statsA_kernel() {
    int t = threadIdx.x;
    int base = blockIdx.x * 32;
    double a = 0.0;
    for (int v = 0; v < 32; v++) a += (double)d_z1stats[(size_t)(base + v) * 128 + t];
    d_z1stats2[blockIdx.x * 128 + t] = a;
}

__global__ __launch_bounds__(128) void stats1_kernel(const float* __restrict__ gamma,
                                                     const float* __restrict__ beta) {
    __shared__ double S[128];
    int t = threadIdx.x;
    double acc = 0.0;
    #pragma unroll 8
    for (int c = 0; c < 64; c++) acc += d_z1stats2[c * 128 + t];
    S[t] = acc;
    __syncthreads();
    if (t < 64) {
        double mean = S[t] / (double)NCOL;
        double var  = S[64 + t] / (double)NCOL - mean * mean;
        float aa = gamma[t] * rsqrtf((float)var + 1e-5f);
        float cc = beta[t] - (float)mean * aa;
        d_a1c1[t] = make_float2(aa, cc);
    }
}

/* ------------------------- 6. GEMM-2: layer-2 only, fused epilogue ------- */
__global__ __launch_bounds__(128, 4) void gemm2_kernel(const float* __restrict__ w2,
                                                       const float* __restrict__ b2,
                                                       float* __restrict__ out) {
    extern __shared__ char smraw[];
    uint32_t smb = smem_u32(smraw);
    float2* ac    = (float2*)(smraw + SM2_AC);
    float*  sbias = (float*)(smraw + SM2_BIAS);
    int tid = threadIdx.x, wid = tid >> 5, lane = tid & 31;

    if (tid < 64) { ac[tid] = d_a1c1[tid]; sbias[tid] = b2[tid]; }
    build_B(smraw, SM2_BHI, SM2_BLO, w2, tid);
    __syncthreads();

    int q = lane & 3;
    uint32_t nB  = ((lane >> 4) * 8) + (lane & 7);
    uint32_t kbB = ((lane >> 3) & 1) * 8;

    for (int t = 0; t < TPC; t++) {
        int T = blockIdx.x * TPC + t;
        #pragma unroll
        for (int mt = 0; mt < 2; mt++) {
            /* reload z1 fragments, BN+relu, pack to A-fragments */
            size_t zb = ((((size_t)T*4 + wid)*2 + mt)*8)*32 + lane;
            uint32_t ahf[4][4];
            #pragma unroll
            for (int kt = 0; kt < 4; kt++)
                #pragma unroll
                for (int half = 0; half < 2; half++) {
                    int j = 2*kt + half;
                    uint2 zz = __ldg(&d_z1h[zb + (size_t)j*32]);
                    float2 p0 = __half22float2(*(__half2*)&zz.x);
                    float2 p1 = __half22float2(*(__half2*)&zz.y);
                    float2 c0 = ac[8*j + 2*q], c1 = ac[8*j + 2*q + 1];
                    float v0 = fmaxf(fmaf(c0.x, p0.x, c0.y), 0.0f);
                    float v1 = fmaxf(fmaf(c1.x, p0.y, c1.y), 0.0f);
                    float v2 = fmaxf(fmaf(c0.x, p1.x, c0.y), 0.0f);
                    float v3 = fmaxf(fmaf(c1.x, p1.y, c1.y), 0.0f);
                    ahf[kt][half*2]     = pkh(v0, v1);
                    ahf[kt][half*2 + 1] = pkh(v2, v3);
                }

            /* layer-2 MMA (2-term fp16) */
            float acc2[8][4];
            #pragma unroll
            for (int j = 0; j < 8; j++)
                #pragma unroll
                for (int v = 0; v < 4; v++) acc2[j][v] = 0.0f;
            #pragma unroll
            for (int kt = 0; kt < 4; kt++) {
                uint32_t bh[4][4], bl[4][4];
                #pragma unroll
                for (int u = 0; u < 4; u++) {
                    uint32_t off = SWZ((nB + u*16)*128 + (kbB + kt*16)*2);
                    ldsm4(smb + SM2_BHI + off, bh[u]);
                    ldsm4(smb + SM2_BLO + off, bl[u]);
                }
                #pragma unroll
                for (int j = 0; j < 8; j++) {
                    int u = j >> 1, h2 = (j & 1) * 2;
                    mma_f16(acc2[j], ahf[kt], bh[u][h2], bh[u][h2+1]);
                    mma_f16(acc2[j], ahf[kt], bl[u][h2], bl[u][h2+1]);
                }
            }

            /* max over this m16 tile (= one point's 16 neighbors) + bias */
            int g  = T * 8 + wid * 2 + mt;
            int bb = g >> 12, ii = g & 4095;
            #pragma unroll
            for (int j = 0; j < 8; j++) {
                float x = fmaxf(acc2[j][0], acc2[j][2]);
                float y = fmaxf(acc2[j][1], acc2[j][3]);
                #pragma unroll
                for (int off = 4; off <= 16; off <<= 1) {
                    x = fmaxf(x, __shfl_xor_sync(0xffffffffu, x, off));
                    y = fmaxf(y, __shfl_xor_sync(0xffffffffu, y, off));
                }
                if (lane < 4) {
                    int c0 = 8*j + 2*lane;
                    out[((size_t)(bb * CH + c0)     << 12) + ii] = x + sbias[c0];
                    out[((size_t)(bb * CH + c0 + 1) << 12) + ii] = y + sbias[c0 + 1];
                }
            }
        }
    }
}

/* ------------------------- launch ---------------------------------------- */
extern "C" void kernel_launch(void* const* d_in, const int* in_sizes, int n_in,
                              void* d_out, int out_size) {
    const float* xyz   = (const float*)d_in[0];
    const float* w1    = (const float*)d_in[1];
    const float* b1    = (const float*)d_in[2];
    const float* w2    = (const float*)d_in[3];
    const float* b2    = (const float*)d_in[4];
    const float* gamma = (const float*)d_in[5];
    const float* beta  = (const float*)d_in[6];
    float* out = (float*)d_out;

    cudaFuncSetAttribute(gemm1_kernel, cudaFuncAttributeMaxDynamicSharedMemorySize, SMEM_G);
    cudaFuncSetAttribute(gemm2_kernel, cudaFuncAttributeMaxDynamicSharedMemorySize, SMEM_G2);

    bucket_kernel<<<BATCH, 1024>>>(xyz);
    knn_kernel<<<dim3(32, BATCH), 128>>>(xyz);
    prep_kernel<<<1, 64>>>(w1, b1, gamma, beta);
    gemm1_kernel<<<NGRID, 128, SMEM_G>>>(w2);
    statsA_kernel<<<64, 128>>>();
    stats1_kernel<<<1, 128>>>(gamma, beta);
    gemm2_kernel<<<NGRID, 128, SMEM_G2>>>(w2, b2, out);
}